// round 9
// baseline (speedup 1.0000x reference)
#include <cuda_runtime.h>
#include <math.h>

#define D        4096
#define KSEL     614              // int(4096 * 0.15)
#define THREADS  256
#define V4PT     4                // float4 per thread
#define NBIN     1024             // positive-float bins: bin = u >> 21
#define CAP      768              // spec candidates: bins [507,509], lambda~508, 12 sigma
#define TCAP     64               // top-2 candidates: x >= 2.5, lambda~25
#define SPEC_LO  507u             // bin(0.875)
#define SPEC_HI  509u             // bin covers up to 1.5
#define TOP2_BIN 513u             // bin(2.5)
#define FULL     0xFFFFFFFFu
#define GAIN     3.0f
#define NEG_INF  (-__int_as_float(0x7F800000))

__global__ void __launch_bounds__(THREADS, 8)
diff_gated_topk_kernel(const float* __restrict__ x, float* __restrict__ out) {
    __shared__ unsigned hist[NBIN];        // [0..255] reused later as L2 hist
    __shared__ unsigned cand[CAP];
    __shared__ unsigned candT[TCAP];
    __shared__ unsigned cand2[32];
    __shared__ unsigned s_ncand, s_nT, s_ncand2, s_run;
    __shared__ unsigned warp_off[THREADS / 32];
    __shared__ float    w_m1[THREADS / 32], w_m2[THREADS / 32];
    __shared__ unsigned s_binid, s_want, s_neg, s_bin2, s_want2, s_thr;
    __shared__ float    s_gain;

    const int t    = threadIdx.x;
    const int lane = t & 31;
    const int warp = t >> 5;
    const size_t base = (size_t)blockIdx.x * D;

    const float4* in4  = (const float4*)(x + base);
    float4*       out4 = (float4*)(out + base);
    uint4*        h4   = (uint4*)hist;

    // ---- Phase 0: zero histogram ----
    h4[t] = make_uint4(0, 0, 0, 0);
    if (t == 0) { s_ncand = 0; s_nT = 0; s_ncand2 = 0; s_neg = 0; }
    __syncthreads();

    // ---- Phase 1: single scan: histogram + speculative candidate gather ----
#pragma unroll
    for (int i = 0; i < V4PT; i++) {
        float4 v = in4[t + i * THREADS];          // default caching: keep in L1 for reuse
        unsigned u[4] = {__float_as_uint(v.x), __float_as_uint(v.y),
                         __float_as_uint(v.z), __float_as_uint(v.w)};
#pragma unroll
        for (int c = 0; c < 4; c++) {
            unsigned b = u[c] >> 21;              // < 1024 iff positive
            if (b < NBIN) atomicAdd(&hist[b], 1u);
            if (b - SPEC_LO <= (SPEC_HI - SPEC_LO)) {
                unsigned p = atomicAdd(&s_ncand, 1u);
                if (p < CAP) cand[p] = u[c];
            }
            if (b >= TOP2_BIN && b < NBIN) {
                unsigned p = atomicAdd(&s_nT, 1u);
                if (p < TCAP) candT[p] = u[c];
            }
        }
    }
    __syncthreads();

    // ---- Phase 2: locate rank-KSEL bin (descending scan over full hist) ----
    const int qb = 4 * (255 - t);                 // t=0 owns the TOP bins
    const uint4 hv = h4[255 - t];
    unsigned h[4] = {hv.x, hv.y, hv.z, hv.w};
    unsigned csum = h[0] + h[1] + h[2] + h[3];

    unsigned inc = csum;
#pragma unroll
    for (int o = 1; o < 32; o <<= 1) {
        unsigned n = __shfl_up_sync(FULL, inc, o);
        if (lane >= o) inc += n;
    }
    if (lane == 31) warp_off[warp] = inc;
    __syncthreads();

    if (t == 0) {
        unsigned run = 0;
#pragma unroll
        for (int w = 0; w < THREADS / 32; w++) {
            unsigned tt = warp_off[w];
            warp_off[w] = run;
            run += tt;
        }
        s_run = run;
        if (run < KSEL) s_neg = 1;                // threshold falls among negatives
    }
    __syncthreads();

    {
        const unsigned excl = warp_off[warp] + inc - csum;
        if (excl < KSEL && KSEL <= excl + csum) { // exactly one thread
            unsigned cum = excl;
#pragma unroll
            for (int j = 3; j >= 0; j--) {
                unsigned c = h[j];
                if (cum + c >= KSEL) { s_binid = (unsigned)(qb + j); s_want = KSEL - cum; break; }
                cum += c;
            }
        }
    }
    __syncthreads();

    // ---- Slow-path determination (uniform across block; ~never taken) ----
    const unsigned use_neg = s_neg;
    const bool slow = use_neg
                   || (s_binid - SPEC_LO > (SPEC_HI - SPEC_LO))
                   || (s_ncand > CAP)
                   || (s_nT < 2) || (s_nT > TCAP);

    if (slow) {
        // exact generic path: rebuild what speculation missed
        if (use_neg) {
            h4[t] = make_uint4(0, 0, 0, 0);
            __syncthreads();
            for (int i = 0; i < V4PT; i++) {
                float4 v = in4[t + i * THREADS];
                unsigned u[4] = {__float_as_uint(v.x), __float_as_uint(v.y),
                                 __float_as_uint(v.z), __float_as_uint(v.w)};
                for (int c = 0; c < 4; c++)
                    if (u[c] >= 0x80000000u) atomicAdd(&hist[(~u[c]) >> 21], 1u);
            }
            __syncthreads();
            if (t == 0) {
                unsigned want = KSEL - s_run, cum = 0;
                for (int b = NBIN - 1; b >= 0; b--) {
                    unsigned c = hist[b];
                    if (cum + c >= want) { s_binid = (unsigned)b; s_want = want - cum; break; }
                    cum += c;
                }
            }
        }
        if (t == 0) s_ncand = 0;
        __syncthreads();

        // exact candidate recollect + full top-2 reduce
        float m1 = NEG_INF, m2 = NEG_INF;
        const unsigned binid = s_binid;
        for (int i = 0; i < V4PT; i++) {
            float4 v = in4[t + i * THREADS];
            float f[4] = {v.x, v.y, v.z, v.w};
            unsigned u[4] = {__float_as_uint(v.x), __float_as_uint(v.y),
                             __float_as_uint(v.z), __float_as_uint(v.w)};
            for (int c = 0; c < 4; c++) {
                float hi = fmaxf(m1, f[c]);
                float lo = fminf(m1, f[c]);
                m2 = fmaxf(m2, lo);
                m1 = hi;
                const bool pos = (u[c] < 0x80000000u);
                const unsigned key = use_neg ? ~u[c] : u[c];
                const bool sel = use_neg ? !pos : pos;
                if (sel && (key >> 21) == binid) {
                    unsigned p = atomicAdd(&s_ncand, 1u);
                    if (p < CAP) cand[p] = key;
                }
            }
        }
#pragma unroll
        for (int o = 16; o > 0; o >>= 1) {
            float a = __shfl_down_sync(FULL, m1, o);
            float b = __shfl_down_sync(FULL, m2, o);
            float hi = fmaxf(m1, a);
            float lo = fminf(m1, a);
            m2 = fmaxf(fmaxf(m2, b), lo);
            m1 = hi;
        }
        if (lane == 0) { w_m1[warp] = m1; w_m2[warp] = m2; }
        __syncthreads();
        if (t == 0) {
            float v1 = w_m1[0], v2 = w_m2[0];
#pragma unroll
            for (int w = 1; w < THREADS / 32; w++) {
                float a = w_m1[w], b = w_m2[w];
                float hi = fmaxf(v1, a);
                float lo = fminf(v1, a);
                v2 = fmaxf(fmaxf(v2, b), lo);
                v1 = hi;
            }
            s_gain = GAIN / (1.0f + __expf(-(v1 - v2))) + 1.0f;
        }
    }
    __syncthreads();

    // ---- Phase 4a: zero L2 hist; hot-path gain (warp 0); build L2 hist ----
    hist[t] = 0;
    __syncthreads();

    const unsigned binid = s_binid;
    unsigned nc = s_ncand; if (nc > CAP) nc = CAP;

    if (!slow && warp == 0) {                     // gain from top-2 candidates
        unsigned nT = s_nT;                        // 2 <= nT <= TCAP here
        float a = (lane < (int)nT)      ? __uint_as_float(candT[lane])      : NEG_INF;
        float b = (lane + 32 < (int)nT) ? __uint_as_float(candT[lane + 32]) : NEG_INF;
        float m1 = fmaxf(a, b);
        float m2 = fminf(a, b);
#pragma unroll
        for (int o = 16; o > 0; o >>= 1) {
            float aa = __shfl_down_sync(FULL, m1, o);
            float bb = __shfl_down_sync(FULL, m2, o);
            float hi = fmaxf(m1, aa);
            float lo = fminf(m1, aa);
            m2 = fmaxf(fmaxf(m2, bb), lo);
            m1 = hi;
        }
        if (lane == 0) s_gain = GAIN / (1.0f + __expf(-(m1 - m2))) + 1.0f;
    }

    for (unsigned ci = t; ci < nc; ci += THREADS) {
        unsigned u = cand[ci];
        if ((u >> 21) == binid) atomicAdd(&hist[(u >> 13) & 0xFFu], 1u);
    }
    __syncthreads();

    // ---- Phase 4b: locate L2 sub-bin (1 bin/thread, descending) ----
    {
        const int b2 = 255 - t;
        unsigned c2 = hist[b2];
        unsigned inc2 = c2;
#pragma unroll
        for (int o = 1; o < 32; o <<= 1) {
            unsigned n = __shfl_up_sync(FULL, inc2, o);
            if (lane >= o) inc2 += n;
        }
        if (lane == 31) warp_off[warp] = inc2;
        __syncthreads();
        unsigned woff = 0;
#pragma unroll
        for (int w = 0; w < THREADS / 32; w++)
            woff += (w < warp) ? warp_off[w] : 0;
        const unsigned excl2 = woff + inc2 - c2;
        const unsigned want = s_want;
        if (excl2 < want && want <= excl2 + c2) {
            s_bin2  = (unsigned)b2;
            s_want2 = want - excl2;
        }
    }
    __syncthreads();

    // ---- Phase 4c: exact select inside sub-bin (expected 1-2 candidates) ----
    {
        const unsigned bin2 = s_bin2;
        for (unsigned ci = t; ci < nc; ci += THREADS) {
            unsigned s = cand[ci];
            if ((s >> 21) == binid && ((s >> 13) & 0xFFu) == bin2) {
                unsigned p = atomicAdd(&s_ncand2, 1u);
                if (p < 32) cand2[p] = s;
            }
        }
    }
    __syncthreads();
    {
        unsigned nc2 = s_ncand2; if (nc2 > 32) nc2 = 32;
        const unsigned want2 = s_want2;
        if (t < (int)nc2) {
            unsigned v = cand2[t];
            unsigned gt = 0, eq = 0;
            for (unsigned j = 0; j < nc2; j++) {
                unsigned u = cand2[j];
                gt += (u > v);
                eq += (u == v);
            }
            if (gt < want2 && gt + eq >= want2) s_thr = v;
        }
    }
    __syncthreads();

    // ---- Phase 5: re-read (L1-resident) + gated scaled write-out ----
    const float thr  = use_neg ? __uint_as_float(~s_thr) : __uint_as_float(s_thr);
    const float gain = s_gain;
#pragma unroll
    for (int i = 0; i < V4PT; i++) {
        float4 v = in4[t + i * THREADS];
        v.x = (v.x >= thr) ? v.x * gain : 0.0f;
        v.y = (v.y >= thr) ? v.y * gain : 0.0f;
        v.z = (v.z >= thr) ? v.z * gain : 0.0f;
        v.w = (v.w >= thr) ? v.w * gain : 0.0f;
        __stcs(&out4[t + i * THREADS], v);
    }
}

extern "C" void kernel_launch(void* const* d_in, const int* in_sizes, int n_in,
                              void* d_out, int out_size) {
    const float* x = (const float*)d_in[0];
    float* out = (float*)d_out;
    const int n_rows = in_sizes[0] / D;   // 16384
    diff_gated_topk_kernel<<<n_rows, THREADS>>>(x, out);
}